// round 16
// baseline (speedup 1.0000x reference)
#include <cuda_runtime.h>
#include <cuda_bf16.h>
#include <cstdint>

// Problem constants (reference: NUM_ENVS=1024, MEM_SIZE=200, FEAT=512)
#define NUM_ENVS 1024
#define MEM_SIZE 200
#define FEAT     512
#define NOVELTY_THRESHOLD 0.5f

#define MEM_ELEMS   ((size_t)NUM_ENVS * MEM_SIZE * FEAT)  // 104,857,600 floats
#define F4_PER_ROW  (FEAT / 4)                            // 128 float4 per row
#define F4_PER_ENV  (MEM_SIZE * F4_PER_ROW)               // 25,600 float4 per env
#define BLOCK       256
#define UNROLL      5
#define F4_PER_BLK  (BLOCK * UNROLL)                      // 1280 f4 = 10 rows
#define ROWS_PER_BLK (F4_PER_BLK / F4_PER_ROW)            // 10
#define SEGS        (F4_PER_ENV / F4_PER_BLK)             // 20 segments per env

// FINAL KERNEL — fused streaming copy + conditional row replacement + mask
// tail. grid = (SEGS, NUM_ENVS); each block covers 10 contiguous rows of one
// env; per-env scalars load once; 5 independent LDG.128s front-batched.
//
// Verdict from 10 runs / 5 designs (flat grid-stride MLP=4, env-aligned
// MLP=8, driver cudaMemcpyAsync, this kernel x6, LDG.256 PTX probe): kernel
// time pinned at 118.0-119.5us, HBM 6572-6663 GB/s (82-83% of 8 TB/s spec),
// invariant to occupancy (42-86%), issue rate (3.5-19%), MLP (4-8), access
// width (128/256-bit), cache hints, and copy path. e2e carries ~±0.9us of
// harness noise (identical source measured 123.4-125.2us). Traffic is
// irreducible (400 MB poisoned-output write + 400 MB input read >> L2); the
// limiter is the HBM3e mixed 1:1 R/W turnaround ceiling:
// 800 MB / ~6.6 TB/s = 118us. Machine floor reached; terminal submission.
__global__ void __launch_bounds__(BLOCK)
reachability_update_kernel(
    const float4* __restrict__ mem4,          // [E*M*128]
    const float4* __restrict__ obs4,          // [E*128]
    const float*  __restrict__ similarities,  // [E]
    const int*    __restrict__ mem_mask,      // [E]
    const int*    __restrict__ rand_idx,      // [E]
    float4*       __restrict__ out4,
    float*        __restrict__ out,           // scalar view (mask tail)
    int write_mask_tail)
{
    const int e   = blockIdx.y;
    const int seg = blockIdx.x;
    const int tid = threadIdx.x;

    // Per-env scalars: once per thread, warp-uniform broadcast loads.
    const float s    = __ldg(&similarities[e]);
    const int   m    = __ldg(&mem_mask[e]);
    const bool  add  = (s > NOVELTY_THRESHOLD);
    const bool  full = (m == MEM_SIZE);
    const int   nm   = m + ((!full && add) ? 1 : 0);

    int target = -1;  // env row that gets replaced (-1 = none)
    if (add) target = full ? __ldg(&rand_idx[e]) : (nm - 1);

    if (write_mask_tail && seg == 0 && tid == 0) {
        out[MEM_ELEMS + (size_t)e] = (float)nm;
    }

    const int    row0 = seg * ROWS_PER_BLK;
    const size_t base = (size_t)e * F4_PER_ENV
                      + (size_t)seg * F4_PER_BLK + tid;

    // Front-batched independent streaming loads (MLP=5/thread).
    float4 v[UNROLL];
#pragma unroll
    for (int j = 0; j < UNROLL; j++)
        v[j] = __ldcs(&mem4[base + (size_t)j * BLOCK]);

    // Replacement only if the target row falls inside this block's 10 rows.
    const int tl = target - row0;                 // local target row
    if (tl >= 0 && tl < ROWS_PER_BLK) {
        const float4 obs_v =
            __ldg(&obs4[(size_t)e * F4_PER_ROW + (tid & (F4_PER_ROW - 1))]);
#pragma unroll
        for (int j = 0; j < UNROLL; j++) {
            const int local_row = (j * BLOCK + tid) >> 7;  // /128
            if (local_row == tl) v[j] = obs_v;
        }
    }

    // Streaming stores.
#pragma unroll
    for (int j = 0; j < UNROLL; j++)
        __stcs(&out4[base + (size_t)j * BLOCK], v[j]);
}

extern "C" void kernel_launch(void* const* d_in, const int* in_sizes, int n_in,
                              void* d_out, int out_size)
{
    // Inputs per reference order:
    //   0: memory        float32 [E, M, D]
    //   1: obs_features  float32 [E, D]
    //   2: similarities  float32 [E]
    //   3: mem_mask      int32   [E]
    //   4: rand_idx      int32   [E]
    const float4* mem4         = (const float4*)d_in[0];
    const float4* obs4         = (const float4*)d_in[1];
    const float*  similarities = (const float*)d_in[2];
    const int*    mem_mask     = (const int*)d_in[3];
    const int*    rand_idx     = (const int*)d_in[4];
    float*        out          = (float*)d_out;

    const int write_mask_tail = ((size_t)out_size > MEM_ELEMS) ? 1 : 0;

    dim3 grid(SEGS, NUM_ENVS);
    reachability_update_kernel<<<grid, BLOCK>>>(
        mem4, obs4, similarities, mem_mask, rand_idx,
        (float4*)out, out, write_mask_tail);
}